// round 14
// baseline (speedup 1.0000x reference)
#include <cuda_runtime.h>
#include <cuda_bf16.h>
#include <cstdint>

#define DIM   128
#define NNB   64
#define WARPS 2        // rows per block (fine-grained load balance)

// 256-bit gather load, L1::no_allocate: gathered rows are consumed once per
// warp and never re-read from L1 — skip the L1 allocate/evict churn entirely.
// Duplicate-index reuse is served by L2 (unaffected by the L1 hint).
__device__ __forceinline__ void ldg256(const float* __restrict__ p, float v[8]) {
    uint32_t u0,u1,u2,u3,u4,u5,u6,u7;
    asm volatile("ld.global.nc.L1::no_allocate.v8.b32 "
                 "{%0,%1,%2,%3,%4,%5,%6,%7}, [%8];"
                 : "=r"(u0),"=r"(u1),"=r"(u2),"=r"(u3),
                   "=r"(u4),"=r"(u5),"=r"(u6),"=r"(u7)
                 : "l"(p));
    v[0]=__uint_as_float(u0); v[1]=__uint_as_float(u1);
    v[2]=__uint_as_float(u2); v[3]=__uint_as_float(u3);
    v[4]=__uint_as_float(u4); v[5]=__uint_as_float(u5);
    v[6]=__uint_as_float(u6); v[7]=__uint_as_float(u7);
}

// Plain v8 load for rel_emb (small, L2/L1-hot; allocation is fine).
__device__ __forceinline__ void ldg256_hot(const float* __restrict__ p, float v[8]) {
    uint32_t u0,u1,u2,u3,u4,u5,u6,u7;
    asm volatile("ld.global.nc.v8.b32 {%0,%1,%2,%3,%4,%5,%6,%7}, [%8];"
                 : "=r"(u0),"=r"(u1),"=r"(u2),"=r"(u3),
                   "=r"(u4),"=r"(u5),"=r"(u6),"=r"(u7)
                 : "l"(p));
    v[0]=__uint_as_float(u0); v[1]=__uint_as_float(u1);
    v[2]=__uint_as_float(u2); v[3]=__uint_as_float(u3);
    v[4]=__uint_as_float(u4); v[5]=__uint_as_float(u5);
    v[6]=__uint_as_float(u6); v[7]=__uint_as_float(u7);
}

__global__ void __launch_bounds__(32 * WARPS, 16)
net_gather_kernel(const int* __restrict__ data_r,
                  const int* __restrict__ data_e,
                  const int* __restrict__ rel,
                  const int* __restrict__ pos_id,
                  const int* __restrict__ neg_id,
                  const float* __restrict__ ent_emb,
                  const float* __restrict__ edge_w,
                  const float* __restrict__ rel_emb,
                  float* __restrict__ out,
                  int B)
{
    const int w    = threadIdx.x >> 5;
    const int lane = threadIdx.x & 31;
    const int b    = blockIdx.x * WARPS + w;

    const int halfsel = lane >> 4;     // row parity this lane serves
    const int sub     = lane & 15;     // 32B sub-block within the 512B row
    const int foff    = sub * 8;

    __shared__ int   s_e[WARPS][NNB];  // entity row index * 128 (float stride)
    __shared__ float s_w[WARPS][NNB];  // softmax weights

    // Stage indices first — gather loads depend only on these.
    const int base = b * NNB;
    if (lane < 16) {
        int4 e4 = __ldg(&((const int4*)(data_e + base))[lane]);
        s_e[w][4 * lane + 0] = e4.x * DIM;
        s_e[w][4 * lane + 1] = e4.y * DIM;
        s_e[w][4 * lane + 2] = e4.z * DIM;
        s_e[w][4 * lane + 3] = e4.w * DIM;
    }
    __syncwarp();

    // Issue the FIRST gather chunk (8 rows) before computing the softmax,
    // hiding the softmax's shfl/exp latency behind the first DRAM round-trip.
    float vpre[4][8];
    #pragma unroll
    for (int k = 0; k < 4; k++)
        ldg256(&ent_emb[s_e[w][2 * k + halfsel] + foff], vpre[k]);

    // Per-row side lookups (independent), also in flight early.
    const float4* __restrict__ emb4 = (const float4*)ent_emb;   // row stride 32
    float4 pv = __ldcg(&emb4[pos_id[b] * (DIM / 4) + lane]);
    float4 nv = __ldcg(&emb4[neg_id[b] * (DIM / 4) + lane]);
    const int relrow = rel[b] * DIM;

    // Warp-local softmax over 64 logits (2 per lane) — overlaps loads above.
    float l0 = __ldg(&edge_w[data_r[base + lane]]);
    float l1 = __ldg(&edge_w[data_r[base + lane + 32]]);
    float m = fmaxf(l0, l1);
    #pragma unroll
    for (int off = 16; off > 0; off >>= 1)
        m = fmaxf(m, __shfl_xor_sync(0xffffffffu, m, off));
    float x0 = __expf(l0 - m);
    float x1 = __expf(l1 - m);
    float s = x0 + x1;
    #pragma unroll
    for (int off = 16; off > 0; off >>= 1)
        s += __shfl_xor_sync(0xffffffffu, s, off);
    float inv = __frcp_rn(s);
    s_w[w][lane]      = x0 * inv;
    s_w[w][lane + 32] = x1 * inv;
    __syncwarp();

    // Gather mainloop: consume prefetched chunk, keep 4 LDG.256 (8 rows, 4KB)
    // in flight per iteration.
    float acc[8] = {0.f,0.f,0.f,0.f,0.f,0.f,0.f,0.f};
    #pragma unroll
    for (int j = 0; j < NNB; j += 8) {
        float v[4][8];
        if (j + 8 < NNB) {
            #pragma unroll
            for (int k = 0; k < 4; k++)
                ldg256(&ent_emb[s_e[w][j + 8 + 2 * k + halfsel] + foff], v[k]);
        }
        #pragma unroll
        for (int k = 0; k < 4; k++) {
            float wt = s_w[w][j + 2 * k + halfsel];
            #pragma unroll
            for (int d = 0; d < 8; d++)
                acc[d] = fmaf(wt, vpre[k][d], acc[d]);
        }
        #pragma unroll
        for (int k = 0; k < 4; k++)
            #pragma unroll
            for (int d = 0; d < 8; d++)
                vpre[k][d] = v[k][d];
    }

    // Combine row parities: lane l and lane l^16 hold the same dims.
    #pragma unroll
    for (int d = 0; d < 8; d++)
        acc[d] += __shfl_xor_sync(0xffffffffu, acc[d], 16);

    float4* out4 = (float4*)out;
    const int BD = B * (DIM / 4);
    const int bd = b * (DIM / 4) + lane;

    // out_t: lanes 0-15 own dims [sub*8, sub*8+8); add rel row (L2-hot).
    if (halfsel == 0) {
        float rv8[8];
        ldg256_hot(&rel_emb[relrow + foff], rv8);
        float4 o0, o1;
        o0.x = acc[0] + rv8[0]; o0.y = acc[1] + rv8[1];
        o0.z = acc[2] + rv8[2]; o0.w = acc[3] + rv8[3];
        o1.x = acc[4] + rv8[4]; o1.y = acc[5] + rv8[5];
        o1.z = acc[6] + rv8[6]; o1.w = acc[7] + rv8[7];
        __stcs(&out4[b * (DIM / 4) + 2 * sub],     o0);
        __stcs(&out4[b * (DIM / 4) + 2 * sub + 1], o1);
    }
    __stcs(&out4[BD + bd],     pv);
    __stcs(&out4[2 * BD + bd], nv);
}

extern "C" void kernel_launch(void* const* d_in, const int* in_sizes, int n_in,
                              void* d_out, int out_size)
{
    const int*   data_r  = (const int*)  d_in[0];
    const int*   data_e  = (const int*)  d_in[1];
    const int*   rel     = (const int*)  d_in[2];
    const int*   pos_id  = (const int*)  d_in[3];
    const int*   neg_id  = (const int*)  d_in[4];
    const float* ent_emb = (const float*)d_in[5];
    const float* edge_w  = (const float*)d_in[6];
    const float* rel_emb = (const float*)d_in[7];
    float* out = (float*)d_out;

    const int B = in_sizes[2];  // rel has B elements

    net_gather_kernel<<<B / WARPS, 32 * WARPS>>>(data_r, data_e, rel,
                                                 pos_id, neg_id,
                                                 ent_emb, edge_w, rel_emb,
                                                 out, B);
}

// round 15
// speedup vs baseline: 1.0156x; 1.0156x over previous
#include <cuda_runtime.h>
#include <cuda_bf16.h>
#include <cstdint>

#define DIM   128
#define NNB   64
#define WARPS 2        // rows per block (fine-grained load balance)

// 256-bit gather load: 8 floats (32B) per lane. A half-warp (16 lanes x 32B)
// covers one full 512B embedding row, so one LDG.256 fetches TWO rows.
__device__ __forceinline__ void ldg256(const float* __restrict__ p, float v[8]) {
    uint32_t u0,u1,u2,u3,u4,u5,u6,u7;
    asm volatile("ld.global.nc.v8.b32 {%0,%1,%2,%3,%4,%5,%6,%7}, [%8];"
                 : "=r"(u0),"=r"(u1),"=r"(u2),"=r"(u3),
                   "=r"(u4),"=r"(u5),"=r"(u6),"=r"(u7)
                 : "l"(p));
    v[0]=__uint_as_float(u0); v[1]=__uint_as_float(u1);
    v[2]=__uint_as_float(u2); v[3]=__uint_as_float(u3);
    v[4]=__uint_as_float(u4); v[5]=__uint_as_float(u5);
    v[6]=__uint_as_float(u6); v[7]=__uint_as_float(u7);
}

__global__ void __launch_bounds__(32 * WARPS, 16)
net_gather_kernel(const int* __restrict__ data_r,
                  const int* __restrict__ data_e,
                  const int* __restrict__ rel,
                  const int* __restrict__ pos_id,
                  const int* __restrict__ neg_id,
                  const float* __restrict__ ent_emb,
                  const float* __restrict__ edge_w,
                  const float* __restrict__ rel_emb,
                  float* __restrict__ out,
                  int B)
{
    const int w    = threadIdx.x >> 5;
    const int lane = threadIdx.x & 31;
    const int b    = blockIdx.x * WARPS + w;

    const int halfsel = lane >> 4;     // row parity this lane serves
    const int sub     = lane & 15;     // 32B sub-block within the 512B row
    const int foff    = sub * 8;

    __shared__ int   s_e[WARPS][NNB];  // entity row index * 128 (float stride)
    __shared__ float s_w[WARPS][NNB];  // softmax weights

    // Stage indices first — gather loads depend only on these.
    const int base = b * NNB;
    if (lane < 16) {
        int4 e4 = __ldg(&((const int4*)(data_e + base))[lane]);
        s_e[w][4 * lane + 0] = e4.x * DIM;
        s_e[w][4 * lane + 1] = e4.y * DIM;
        s_e[w][4 * lane + 2] = e4.z * DIM;
        s_e[w][4 * lane + 3] = e4.w * DIM;
    }
    __syncwarp();

    // Issue the FIRST gather chunk (8 rows) before computing the softmax,
    // hiding the softmax's shfl/exp latency behind the first DRAM round-trip.
    float vpre[4][8];
    #pragma unroll
    for (int k = 0; k < 4; k++)
        ldg256(&ent_emb[s_e[w][2 * k + halfsel] + foff], vpre[k]);

    // Per-row side lookups (independent), also in flight early.
    const float4* __restrict__ emb4 = (const float4*)ent_emb;   // row stride 32
    float4 pv = __ldcg(&emb4[pos_id[b] * (DIM / 4) + lane]);
    float4 nv = __ldcg(&emb4[neg_id[b] * (DIM / 4) + lane]);
    const int relrow = rel[b] * DIM;

    // Warp-local softmax over 64 logits (2 per lane) — overlaps loads above.
    float l0 = __ldg(&edge_w[data_r[base + lane]]);
    float l1 = __ldg(&edge_w[data_r[base + lane + 32]]);
    float m = fmaxf(l0, l1);
    #pragma unroll
    for (int off = 16; off > 0; off >>= 1)
        m = fmaxf(m, __shfl_xor_sync(0xffffffffu, m, off));
    float x0 = __expf(l0 - m);
    float x1 = __expf(l1 - m);
    float s = x0 + x1;
    #pragma unroll
    for (int off = 16; off > 0; off >>= 1)
        s += __shfl_xor_sync(0xffffffffu, s, off);
    float inv = __frcp_rn(s);
    s_w[w][lane]      = x0 * inv;
    s_w[w][lane + 32] = x1 * inv;
    __syncwarp();

    // Gather mainloop: consume prefetched chunk, keep 4 LDG.256 (8 rows, 4KB)
    // in flight per iteration.
    float acc[8] = {0.f,0.f,0.f,0.f,0.f,0.f,0.f,0.f};
    #pragma unroll
    for (int j = 0; j < NNB; j += 8) {
        float v[4][8];
        if (j + 8 < NNB) {
            #pragma unroll
            for (int k = 0; k < 4; k++)
                ldg256(&ent_emb[s_e[w][j + 8 + 2 * k + halfsel] + foff], v[k]);
        }
        #pragma unroll
        for (int k = 0; k < 4; k++) {
            float wt = s_w[w][j + 2 * k + halfsel];
            #pragma unroll
            for (int d = 0; d < 8; d++)
                acc[d] = fmaf(wt, vpre[k][d], acc[d]);
        }
        #pragma unroll
        for (int k = 0; k < 4; k++)
            #pragma unroll
            for (int d = 0; d < 8; d++)
                vpre[k][d] = v[k][d];
    }

    // Combine row parities: lane l and lane l^16 hold the same dims.
    #pragma unroll
    for (int d = 0; d < 8; d++)
        acc[d] += __shfl_xor_sync(0xffffffffu, acc[d], 16);

    float4* out4 = (float4*)out;
    const int BD = B * (DIM / 4);
    const int bd = b * (DIM / 4) + lane;

    // out_t: lanes 0-15 own dims [sub*8, sub*8+8); add rel row (L2-hot).
    if (halfsel == 0) {
        float rv8[8];
        ldg256(&rel_emb[relrow + foff], rv8);
        float4 o0, o1;
        o0.x = acc[0] + rv8[0]; o0.y = acc[1] + rv8[1];
        o0.z = acc[2] + rv8[2]; o0.w = acc[3] + rv8[3];
        o1.x = acc[4] + rv8[4]; o1.y = acc[5] + rv8[5];
        o1.z = acc[6] + rv8[6]; o1.w = acc[7] + rv8[7];
        __stcs(&out4[b * (DIM / 4) + 2 * sub],     o0);
        __stcs(&out4[b * (DIM / 4) + 2 * sub + 1], o1);
    }
    __stcs(&out4[BD + bd],     pv);
    __stcs(&out4[2 * BD + bd], nv);
}

extern "C" void kernel_launch(void* const* d_in, const int* in_sizes, int n_in,
                              void* d_out, int out_size)
{
    const int*   data_r  = (const int*)  d_in[0];
    const int*   data_e  = (const int*)  d_in[1];
    const int*   rel     = (const int*)  d_in[2];
    const int*   pos_id  = (const int*)  d_in[3];
    const int*   neg_id  = (const int*)  d_in[4];
    const float* ent_emb = (const float*)d_in[5];
    const float* edge_w  = (const float*)d_in[6];
    const float* rel_emb = (const float*)d_in[7];
    float* out = (float*)d_out;

    const int B = in_sizes[2];  // rel has B elements

    net_gather_kernel<<<B / WARPS, 32 * WARPS>>>(data_r, data_e, rel,
                                                 pos_id, neg_id,
                                                 ent_emb, edge_w, rel_emb,
                                                 out, B);
}

// round 16
// speedup vs baseline: 1.0172x; 1.0016x over previous
#include <cuda_runtime.h>
#include <cuda_bf16.h>
#include <cstdint>

#define DIM   128
#define NNB   64
#define WARPS 2        // rows per block (fine-grained load balance)

// 256-bit gather load: 8 floats (32B) per lane. A half-warp (16 lanes x 32B)
// covers one full 512B embedding row, so one LDG.256 fetches TWO rows.
__device__ __forceinline__ void ldg256(const float* __restrict__ p, float v[8]) {
    uint32_t u0,u1,u2,u3,u4,u5,u6,u7;
    asm volatile("ld.global.nc.v8.b32 {%0,%1,%2,%3,%4,%5,%6,%7}, [%8];"
                 : "=r"(u0),"=r"(u1),"=r"(u2),"=r"(u3),
                   "=r"(u4),"=r"(u5),"=r"(u6),"=r"(u7)
                 : "l"(p));
    v[0]=__uint_as_float(u0); v[1]=__uint_as_float(u1);
    v[2]=__uint_as_float(u2); v[3]=__uint_as_float(u3);
    v[4]=__uint_as_float(u4); v[5]=__uint_as_float(u5);
    v[6]=__uint_as_float(u6); v[7]=__uint_as_float(u7);
}

__global__ void __launch_bounds__(32 * WARPS, 16)
net_gather_kernel(const int* __restrict__ data_r,
                  const int* __restrict__ data_e,
                  const int* __restrict__ rel,
                  const int* __restrict__ pos_id,
                  const int* __restrict__ neg_id,
                  const float* __restrict__ ent_emb,
                  const float* __restrict__ edge_w,
                  const float* __restrict__ rel_emb,
                  float* __restrict__ out,
                  int B)
{
    const int w    = threadIdx.x >> 5;
    const int lane = threadIdx.x & 31;
    const int b    = blockIdx.x * WARPS + w;

    const int halfsel = lane >> 4;     // row parity this lane serves
    const int sub     = lane & 15;     // 32B sub-block within the 512B row
    const int foff    = sub * 8;

    __shared__ int   s_e[WARPS][NNB];  // entity row index * 128 (float stride)
    __shared__ float s_w[WARPS][NNB];  // softmax weights

    // Stage indices first — gather loads depend only on these.
    const int base = b * NNB;
    if (lane < 16) {
        int4 e4 = __ldg(&((const int4*)(data_e + base))[lane]);
        s_e[w][4 * lane + 0] = e4.x * DIM;
        s_e[w][4 * lane + 1] = e4.y * DIM;
        s_e[w][4 * lane + 2] = e4.z * DIM;
        s_e[w][4 * lane + 3] = e4.w * DIM;
    }
    __syncwarp();

    // Issue the FIRST gather chunk (8 rows) before computing the softmax,
    // hiding the softmax's shfl/exp latency behind the first DRAM round-trip.
    float vpre[4][8];
    #pragma unroll
    for (int k = 0; k < 4; k++)
        ldg256(&ent_emb[s_e[w][2 * k + halfsel] + foff], vpre[k]);

    // Per-row side lookups (independent), also in flight early.
    const float4* __restrict__ emb4 = (const float4*)ent_emb;   // row stride 32
    float4 pv = __ldcg(&emb4[pos_id[b] * (DIM / 4) + lane]);
    float4 nv = __ldcg(&emb4[neg_id[b] * (DIM / 4) + lane]);
    const int relrow = rel[b] * DIM;

    // Warp-local softmax over 64 logits (2 per lane) — overlaps loads above.
    float l0 = __ldg(&edge_w[data_r[base + lane]]);
    float l1 = __ldg(&edge_w[data_r[base + lane + 32]]);
    float m = fmaxf(l0, l1);
    #pragma unroll
    for (int off = 16; off > 0; off >>= 1)
        m = fmaxf(m, __shfl_xor_sync(0xffffffffu, m, off));
    float x0 = __expf(l0 - m);
    float x1 = __expf(l1 - m);
    float s = x0 + x1;
    #pragma unroll
    for (int off = 16; off > 0; off >>= 1)
        s += __shfl_xor_sync(0xffffffffu, s, off);
    float inv = __frcp_rn(s);
    s_w[w][lane]      = x0 * inv;
    s_w[w][lane + 32] = x1 * inv;
    __syncwarp();

    // Gather mainloop: consume prefetched chunk, keep 4 LDG.256 (8 rows, 4KB)
    // in flight per iteration.
    float acc[8] = {0.f,0.f,0.f,0.f,0.f,0.f,0.f,0.f};
    #pragma unroll
    for (int j = 0; j < NNB; j += 8) {
        float v[4][8];
        if (j + 8 < NNB) {
            #pragma unroll
            for (int k = 0; k < 4; k++)
                ldg256(&ent_emb[s_e[w][j + 8 + 2 * k + halfsel] + foff], v[k]);
        }
        #pragma unroll
        for (int k = 0; k < 4; k++) {
            float wt = s_w[w][j + 2 * k + halfsel];
            #pragma unroll
            for (int d = 0; d < 8; d++)
                acc[d] = fmaf(wt, vpre[k][d], acc[d]);
        }
        #pragma unroll
        for (int k = 0; k < 4; k++)
            #pragma unroll
            for (int d = 0; d < 8; d++)
                vpre[k][d] = v[k][d];
    }

    // Combine row parities: lane l and lane l^16 hold the same dims.
    #pragma unroll
    for (int d = 0; d < 8; d++)
        acc[d] += __shfl_xor_sync(0xffffffffu, acc[d], 16);

    float4* out4 = (float4*)out;
    const int BD = B * (DIM / 4);
    const int bd = b * (DIM / 4) + lane;

    // out_t: lanes 0-15 own dims [sub*8, sub*8+8); add rel row (L2-hot).
    if (halfsel == 0) {
        float rv8[8];
        ldg256(&rel_emb[relrow + foff], rv8);
        float4 o0, o1;
        o0.x = acc[0] + rv8[0]; o0.y = acc[1] + rv8[1];
        o0.z = acc[2] + rv8[2]; o0.w = acc[3] + rv8[3];
        o1.x = acc[4] + rv8[4]; o1.y = acc[5] + rv8[5];
        o1.z = acc[6] + rv8[6]; o1.w = acc[7] + rv8[7];
        __stcs(&out4[b * (DIM / 4) + 2 * sub],     o0);
        __stcs(&out4[b * (DIM / 4) + 2 * sub + 1], o1);
    }
    __stcs(&out4[BD + bd],     pv);
    __stcs(&out4[2 * BD + bd], nv);
}

extern "C" void kernel_launch(void* const* d_in, const int* in_sizes, int n_in,
                              void* d_out, int out_size)
{
    const int*   data_r  = (const int*)  d_in[0];
    const int*   data_e  = (const int*)  d_in[1];
    const int*   rel     = (const int*)  d_in[2];
    const int*   pos_id  = (const int*)  d_in[3];
    const int*   neg_id  = (const int*)  d_in[4];
    const float* ent_emb = (const float*)d_in[5];
    const float* edge_w  = (const float*)d_in[6];
    const float* rel_emb = (const float*)d_in[7];
    float* out = (float*)d_out;

    const int B = in_sizes[2];  // rel has B elements

    net_gather_kernel<<<B / WARPS, 32 * WARPS>>>(data_r, data_e, rel,
                                                 pos_id, neg_id,
                                                 ent_emb, edge_w, rel_emb,
                                                 out, B);
}